// round 10
// baseline (speedup 1.0000x reference)
#include <cuda_runtime.h>
#include <cstdint>

#define D        128
#define MAX_OUT  100000
#define M_PAD    100352   // 784*128: tile-overrun padding for g_S reads

// Scratch (allocation-free rule: __device__ globals; zero-initialized)
__device__ float g_S[(size_t)M_PAD * D];   // segment sums (pad rows stay zero)
__device__ float g_Wt[D * D];              // W transposed: Wt[n][k] = W[k][n]
__device__ int   g_row_start[MAX_OUT + 1];

// ---------------------------------------------------------------------------
// helpers
// ---------------------------------------------------------------------------
static __device__ __forceinline__ uint32_t f2tf32(float f) {
    uint32_t r;
    asm("cvt.rna.tf32.f32 %0, %1;" : "=r"(r) : "f"(f));
    return r;
}
static __device__ __forceinline__ void mma_tf32(
    float& c0, float& c1, float& c2, float& c3,
    uint32_t a0, uint32_t a1, uint32_t a2, uint32_t a3,
    uint32_t b0, uint32_t b1)
{
    asm volatile(
        "mma.sync.aligned.m16n8k8.row.col.f32.tf32.tf32.f32 "
        "{%0,%1,%2,%3}, {%4,%5,%6,%7}, {%8,%9}, {%0,%1,%2,%3};"
        : "+f"(c0), "+f"(c1), "+f"(c2), "+f"(c3)
        : "r"(a0), "r"(a1), "r"(a2), "r"(a3), "r"(b0), "r"(b1));
}

// ---------------------------------------------------------------------------
// transpose W (128x128) into g_Wt.  grid=16 (4x4 tiles), block=(32,8)
// ---------------------------------------------------------------------------
__global__ void transpose_W(const float* __restrict__ W) {
    __shared__ float t[32][33];
    int bx = blockIdx.x & 3, by = blockIdx.x >> 2;
    int x = bx * 32 + threadIdx.x;
    #pragma unroll
    for (int i = 0; i < 4; ++i) {
        int y = by * 32 + threadIdx.y * 4 + i;
        t[threadIdx.y * 4 + i][threadIdx.x] = W[y * D + x];
    }
    __syncthreads();
    #pragma unroll
    for (int i = 0; i < 4; ++i) {
        int n = bx * 32 + threadIdx.y * 4 + i;
        g_Wt[n * D + by * 32 + threadIdx.x] = t[threadIdx.x][threadIdx.y * 4 + i];
    }
}

// ---------------------------------------------------------------------------
// segment CSR construction
// ---------------------------------------------------------------------------
__global__ void init_row_start(int n_out, int E) {
    int i = blockIdx.x * blockDim.x + threadIdx.x;
    if (i <= n_out) g_row_start[i] = E;
}
__global__ void mark_boundaries(const int* __restrict__ seg, int E) {
    int e = blockIdx.x * blockDim.x + threadIdx.x;
    if (e >= E) return;
    int s  = seg[e];
    int sp = (e == 0) ? -1 : seg[e - 1];
    for (int t = sp + 1; t <= s; ++t) g_row_start[t] = e;
}

// ---------------------------------------------------------------------------
// warp-per-segment gather-sum with coalesced index prefetch.
// Lane l owns float4 slice [4l,4l+4). One coalesced load fetches up to 32
// edge indices into registers; value-load addresses then come from shfl only
// (no memory dependency in the loop). Segments >32 edges take a rare tail.
// ---------------------------------------------------------------------------
__global__ __launch_bounds__(256) void seg_gather_sum(
    const float* __restrict__ values,
    const int* __restrict__ gidx,
    int n_out, int E)
{
    int warp = (blockIdx.x * blockDim.x + threadIdx.x) >> 5;
    if (warp >= n_out) return;
    int lane = threadIdx.x & 31;
    int c = lane * 4;

    int e0 = g_row_start[warp];
    int e1 = g_row_start[warp + 1];
    int cnt = e1 - e0;

    // one coalesced 128B index load covers up to 32 edges
    int ei = e0 + lane;
    int idx_l = (ei < E) ? __ldg(gidx + ei) : 0;

    float4 a0 = make_float4(0.f, 0.f, 0.f, 0.f);
    float4 a1 = make_float4(0.f, 0.f, 0.f, 0.f);
    float4 a2 = make_float4(0.f, 0.f, 0.f, 0.f);
    float4 a3 = make_float4(0.f, 0.f, 0.f, 0.f);

    int n32 = cnt < 32 ? cnt : 32;
    int j = 0;
    for (; j + 4 <= n32; j += 4) {
        long long i0 = (long long)__shfl_sync(0xFFFFFFFFu, idx_l, j);
        long long i1 = (long long)__shfl_sync(0xFFFFFFFFu, idx_l, j + 1);
        long long i2 = (long long)__shfl_sync(0xFFFFFFFFu, idx_l, j + 2);
        long long i3 = (long long)__shfl_sync(0xFFFFFFFFu, idx_l, j + 3);
        float4 v0 = __ldg(reinterpret_cast<const float4*>(values + i0 * D + c));
        float4 v1 = __ldg(reinterpret_cast<const float4*>(values + i1 * D + c));
        float4 v2 = __ldg(reinterpret_cast<const float4*>(values + i2 * D + c));
        float4 v3 = __ldg(reinterpret_cast<const float4*>(values + i3 * D + c));
        a0.x += v0.x; a0.y += v0.y; a0.z += v0.z; a0.w += v0.w;
        a1.x += v1.x; a1.y += v1.y; a1.z += v1.z; a1.w += v1.w;
        a2.x += v2.x; a2.y += v2.y; a2.z += v2.z; a2.w += v2.w;
        a3.x += v3.x; a3.y += v3.y; a3.z += v3.z; a3.w += v3.w;
    }
    for (; j < n32; ++j) {
        long long i0 = (long long)__shfl_sync(0xFFFFFFFFu, idx_l, j);
        float4 v0 = __ldg(reinterpret_cast<const float4*>(values + i0 * D + c));
        a0.x += v0.x; a0.y += v0.y; a0.z += v0.z; a0.w += v0.w;
    }

    // rare long-segment tail (cnt > 32): broadcast index loads
    for (int e = e0 + 32; e < e1; ++e) {
        long long i0 = (long long)__ldg(gidx + e);
        float4 v0 = __ldg(reinterpret_cast<const float4*>(values + i0 * D + c));
        a1.x += v0.x; a1.y += v0.y; a1.z += v0.z; a1.w += v0.w;
    }

    float4 acc;
    acc.x = (a0.x + a1.x) + (a2.x + a3.x);
    acc.y = (a0.y + a1.y) + (a2.y + a3.y);
    acc.z = (a0.z + a1.z) + (a2.z + a3.z);
    acc.w = (a0.w + a1.w) + (a2.w + a3.w);
    *reinterpret_cast<float4*>(g_S + (size_t)warp * D + c) = acc;
}

// ---------------------------------------------------------------------------
// tf32 mma.sync GEMM + tanh (byte-identical to the 129.3us baseline).
// CTA: 128(M) x 128(N), K chunked by 64. 8 warps: (wid&3)->m32, (wid>>2)->n64.
// Smem padded [128][68]: fragment loads are bank-conflict-free.
// ---------------------------------------------------------------------------
#define BK      64
#define LDS_PAD 68                       // 64 + 4 floats
#define AS_FLOATS (128 * LDS_PAD)
#define SMEM_FLOATS (2 * AS_FLOATS)      // As + Bs

__global__ __launch_bounds__(256, 2) void gemm_tanh_mma(
    float* __restrict__ out, int M)
{
    extern __shared__ float smem[];
    float* As = smem;                    // [128][68] tf32 bits (as float storage)
    float* Bs = smem + AS_FLOATS;        // [128][68]

    int tid  = threadIdx.x;
    int wid  = tid >> 5;
    int lane = tid & 31;
    int wr   = (wid & 3) * 32;           // warp m offset
    int wc   = (wid >> 2) * 64;          // warp n offset
    int gq   = lane >> 2;                // groupID 0..7
    int tg   = lane & 3;                 // thread-in-group 0..3

    int block_row = blockIdx.x * 128;

    float acc[2][8][4];
    #pragma unroll
    for (int mt = 0; mt < 2; ++mt)
        #pragma unroll
        for (int nt = 0; nt < 8; ++nt)
            #pragma unroll
            for (int q = 0; q < 4; ++q) acc[mt][nt][q] = 0.f;

    for (int kc = 0; kc < 2; ++kc) {
        // ---- stage A and B k-chunk, converting to tf32 ----
        __syncthreads();
        #pragma unroll
        for (int i = 0; i < 8; ++i) {
            int f   = i * 256 + tid;     // 0..2047
            int row = f >> 4;
            int kq  = f & 15;
            float4 va = __ldg(reinterpret_cast<const float4*>(
                g_S + (size_t)(block_row + row) * D + kc * BK + kq * 4));
            uint4 ta = make_uint4(f2tf32(va.x), f2tf32(va.y), f2tf32(va.z), f2tf32(va.w));
            *reinterpret_cast<uint4*>(As + row * LDS_PAD + kq * 4) = ta;

            float4 vb = __ldg(reinterpret_cast<const float4*>(
                g_Wt + (size_t)row * D + kc * BK + kq * 4));
            uint4 tb = make_uint4(f2tf32(vb.x), f2tf32(vb.y), f2tf32(vb.z), f2tf32(vb.w));
            *reinterpret_cast<uint4*>(Bs + row * LDS_PAD + kq * 4) = tb;
        }
        __syncthreads();

        // ---- 8 k-steps of k=8 ----
        #pragma unroll
        for (int ks = 0; ks < 8; ++ks) {
            int k0 = ks * 8;
            uint32_t a[2][4];
            #pragma unroll
            for (int mt = 0; mt < 2; ++mt) {
                const uint32_t* ap = reinterpret_cast<const uint32_t*>(
                    As + (wr + mt * 16 + gq) * LDS_PAD + k0 + tg);
                a[mt][0] = ap[0];
                a[mt][2] = ap[4];
                const uint32_t* ap8 = reinterpret_cast<const uint32_t*>(
                    As + (wr + mt * 16 + gq + 8) * LDS_PAD + k0 + tg);
                a[mt][1] = ap8[0];
                a[mt][3] = ap8[4];
            }
            uint32_t b[8][2];
            #pragma unroll
            for (int nt = 0; nt < 8; ++nt) {
                const uint32_t* bp = reinterpret_cast<const uint32_t*>(
                    Bs + (wc + nt * 8 + gq) * LDS_PAD + k0 + tg);
                b[nt][0] = bp[0];
                b[nt][1] = bp[4];
            }
            #pragma unroll
            for (int mt = 0; mt < 2; ++mt)
                #pragma unroll
                for (int nt = 0; nt < 8; ++nt)
                    mma_tf32(acc[mt][nt][0], acc[mt][nt][1],
                             acc[mt][nt][2], acc[mt][nt][3],
                             a[mt][0], a[mt][1], a[mt][2], a[mt][3],
                             b[nt][0], b[nt][1]);
        }
    }

    // ---- epilogue: tanh + float2 stores ----
    #pragma unroll
    for (int mt = 0; mt < 2; ++mt) {
        int r0 = block_row + wr + mt * 16 + gq;
        int r1 = r0 + 8;
        #pragma unroll
        for (int nt = 0; nt < 8; ++nt) {
            int col = wc + nt * 8 + tg * 2;
            if (r0 < M) {
                float2 o0;
                o0.x = tanhf(acc[mt][nt][0]);
                o0.y = tanhf(acc[mt][nt][1]);
                *reinterpret_cast<float2*>(out + (size_t)r0 * D + col) = o0;
            }
            if (r1 < M) {
                float2 o1;
                o1.x = tanhf(acc[mt][nt][2]);
                o1.y = tanhf(acc[mt][nt][3]);
                *reinterpret_cast<float2*>(out + (size_t)r1 * D + col) = o1;
            }
        }
    }
}

// ---------------------------------------------------------------------------
// Launch
// ---------------------------------------------------------------------------
extern "C" void kernel_launch(void* const* d_in, const int* in_sizes, int n_in,
                              void* d_out, int out_size)
{
    const float* values = (const float*)d_in[0];   // [N_SRC, 128] f32
    const float* Wmat   = (const float*)d_in[1];   // [128, 128] f32
    const int*   gidx   = (const int*)d_in[2];     // [E] int32
    const int*   seg    = (const int*)d_in[3];     // [E] int32, sorted

    int E     = in_sizes[2];
    int n_out = out_size / D;
    float* out = (float*)d_out;

    static int smem_set = 0;
    if (!smem_set) {
        cudaFuncSetAttribute(gemm_tanh_mma,
                             cudaFuncAttributeMaxDynamicSharedMemorySize,
                             SMEM_FLOATS * (int)sizeof(float));
        smem_set = 1;
    }

    transpose_W<<<16, dim3(32, 8)>>>(Wmat);
    init_row_start<<<(n_out + 256) / 256, 256>>>(n_out, E);
    mark_boundaries<<<(E + 255) / 256, 256>>>(seg, E);
    seg_gather_sum<<<(n_out * 32 + 255) / 256, 256>>>(values, gidx, n_out, E);
    gemm_tanh_mma<<<(n_out + 127) / 128, 256, SMEM_FLOATS * sizeof(float)>>>(out, n_out);
}

// round 12
// speedup vs baseline: 1.0004x; 1.0004x over previous
#include <cuda_runtime.h>
#include <cstdint>

#define D        128
#define MAX_OUT  100000
#define M_PAD    100352   // 784*128: tile-overrun padding for g_S reads

// Scratch (allocation-free rule: __device__ globals; zero-initialized)
__device__ float g_S[(size_t)M_PAD * D];   // segment sums (pad rows stay zero)
__device__ float g_Wt[D * D];              // W transposed: Wt[n][k] = W[k][n]
__device__ int   g_row_start[MAX_OUT + 1];

// ---------------------------------------------------------------------------
// helpers
// ---------------------------------------------------------------------------
static __device__ __forceinline__ uint32_t f2tf32(float f) {
    uint32_t r;
    asm("cvt.rna.tf32.f32 %0, %1;" : "=r"(r) : "f"(f));
    return r;
}
static __device__ __forceinline__ void mma_tf32(
    float& c0, float& c1, float& c2, float& c3,
    uint32_t a0, uint32_t a1, uint32_t a2, uint32_t a3,
    uint32_t b0, uint32_t b1)
{
    asm volatile(
        "mma.sync.aligned.m16n8k8.row.col.f32.tf32.tf32.f32 "
        "{%0,%1,%2,%3}, {%4,%5,%6,%7}, {%8,%9}, {%0,%1,%2,%3};"
        : "+f"(c0), "+f"(c1), "+f"(c2), "+f"(c3)
        : "r"(a0), "r"(a1), "r"(a2), "r"(a3), "r"(b0), "r"(b1));
}

// ---------------------------------------------------------------------------
// transpose W (128x128) into g_Wt.  grid=16 (4x4 tiles), block=(32,8)
// ---------------------------------------------------------------------------
__global__ void transpose_W(const float* __restrict__ W) {
    __shared__ float t[32][33];
    int bx = blockIdx.x & 3, by = blockIdx.x >> 2;
    int x = bx * 32 + threadIdx.x;
    #pragma unroll
    for (int i = 0; i < 4; ++i) {
        int y = by * 32 + threadIdx.y * 4 + i;
        t[threadIdx.y * 4 + i][threadIdx.x] = W[y * D + x];
    }
    __syncthreads();
    #pragma unroll
    for (int i = 0; i < 4; ++i) {
        int n = bx * 32 + threadIdx.y * 4 + i;
        g_Wt[n * D + by * 32 + threadIdx.x] = t[threadIdx.x][threadIdx.y * 4 + i];
    }
}

// ---------------------------------------------------------------------------
// segment CSR construction
// ---------------------------------------------------------------------------
__global__ void init_row_start(int n_out, int E) {
    int i = blockIdx.x * blockDim.x + threadIdx.x;
    if (i <= n_out) g_row_start[i] = E;
}
__global__ void mark_boundaries(const int* __restrict__ seg, int E) {
    int e = blockIdx.x * blockDim.x + threadIdx.x;
    if (e >= E) return;
    int s  = seg[e];
    int sp = (e == 0) ? -1 : seg[e - 1];
    for (int t = sp + 1; t <= s; ++t) g_row_start[t] = e;
}

// ---------------------------------------------------------------------------
// warp-per-segment gather-sum with coalesced index prefetch.
// Lane l owns float4 slice [4l,4l+4). One coalesced load fetches up to 32
// edge indices into registers; value-load addresses then come from shfl only
// (no memory dependency in the loop). Segments >32 edges take a rare tail.
// ---------------------------------------------------------------------------
__global__ __launch_bounds__(256) void seg_gather_sum(
    const float* __restrict__ values,
    const int* __restrict__ gidx,
    int n_out, int E)
{
    int warp = (blockIdx.x * blockDim.x + threadIdx.x) >> 5;
    if (warp >= n_out) return;
    int lane = threadIdx.x & 31;
    int c = lane * 4;

    int e0 = g_row_start[warp];
    int e1 = g_row_start[warp + 1];
    int cnt = e1 - e0;

    // one coalesced 128B index load covers up to 32 edges
    int ei = e0 + lane;
    int idx_l = (ei < E) ? __ldg(gidx + ei) : 0;

    float4 a0 = make_float4(0.f, 0.f, 0.f, 0.f);
    float4 a1 = make_float4(0.f, 0.f, 0.f, 0.f);
    float4 a2 = make_float4(0.f, 0.f, 0.f, 0.f);
    float4 a3 = make_float4(0.f, 0.f, 0.f, 0.f);

    int n32 = cnt < 32 ? cnt : 32;
    int j = 0;
    for (; j + 4 <= n32; j += 4) {
        long long i0 = (long long)__shfl_sync(0xFFFFFFFFu, idx_l, j);
        long long i1 = (long long)__shfl_sync(0xFFFFFFFFu, idx_l, j + 1);
        long long i2 = (long long)__shfl_sync(0xFFFFFFFFu, idx_l, j + 2);
        long long i3 = (long long)__shfl_sync(0xFFFFFFFFu, idx_l, j + 3);
        float4 v0 = __ldg(reinterpret_cast<const float4*>(values + i0 * D + c));
        float4 v1 = __ldg(reinterpret_cast<const float4*>(values + i1 * D + c));
        float4 v2 = __ldg(reinterpret_cast<const float4*>(values + i2 * D + c));
        float4 v3 = __ldg(reinterpret_cast<const float4*>(values + i3 * D + c));
        a0.x += v0.x; a0.y += v0.y; a0.z += v0.z; a0.w += v0.w;
        a1.x += v1.x; a1.y += v1.y; a1.z += v1.z; a1.w += v1.w;
        a2.x += v2.x; a2.y += v2.y; a2.z += v2.z; a2.w += v2.w;
        a3.x += v3.x; a3.y += v3.y; a3.z += v3.z; a3.w += v3.w;
    }
    for (; j < n32; ++j) {
        long long i0 = (long long)__shfl_sync(0xFFFFFFFFu, idx_l, j);
        float4 v0 = __ldg(reinterpret_cast<const float4*>(values + i0 * D + c));
        a0.x += v0.x; a0.y += v0.y; a0.z += v0.z; a0.w += v0.w;
    }

    // rare long-segment tail (cnt > 32): broadcast index loads
    for (int e = e0 + 32; e < e1; ++e) {
        long long i0 = (long long)__ldg(gidx + e);
        float4 v0 = __ldg(reinterpret_cast<const float4*>(values + i0 * D + c));
        a1.x += v0.x; a1.y += v0.y; a1.z += v0.z; a1.w += v0.w;
    }

    float4 acc;
    acc.x = (a0.x + a1.x) + (a2.x + a3.x);
    acc.y = (a0.y + a1.y) + (a2.y + a3.y);
    acc.z = (a0.z + a1.z) + (a2.z + a3.z);
    acc.w = (a0.w + a1.w) + (a2.w + a3.w);
    *reinterpret_cast<float4*>(g_S + (size_t)warp * D + c) = acc;
}

// ---------------------------------------------------------------------------
// tf32 mma.sync GEMM + tanh (byte-identical to the 129.3us baseline).
// CTA: 128(M) x 128(N), K chunked by 64. 8 warps: (wid&3)->m32, (wid>>2)->n64.
// Smem padded [128][68]: fragment loads are bank-conflict-free.
// ---------------------------------------------------------------------------
#define BK      64
#define LDS_PAD 68                       // 64 + 4 floats
#define AS_FLOATS (128 * LDS_PAD)
#define SMEM_FLOATS (2 * AS_FLOATS)      // As + Bs

__global__ __launch_bounds__(256, 2) void gemm_tanh_mma(
    float* __restrict__ out, int M)
{
    extern __shared__ float smem[];
    float* As = smem;                    // [128][68] tf32 bits (as float storage)
    float* Bs = smem + AS_FLOATS;        // [128][68]

    int tid  = threadIdx.x;
    int wid  = tid >> 5;
    int lane = tid & 31;
    int wr   = (wid & 3) * 32;           // warp m offset
    int wc   = (wid >> 2) * 64;          // warp n offset
    int gq   = lane >> 2;                // groupID 0..7
    int tg   = lane & 3;                 // thread-in-group 0..3

    int block_row = blockIdx.x * 128;

    float acc[2][8][4];
    #pragma unroll
    for (int mt = 0; mt < 2; ++mt)
        #pragma unroll
        for (int nt = 0; nt < 8; ++nt)
            #pragma unroll
            for (int q = 0; q < 4; ++q) acc[mt][nt][q] = 0.f;

    for (int kc = 0; kc < 2; ++kc) {
        // ---- stage A and B k-chunk, converting to tf32 ----
        __syncthreads();
        #pragma unroll
        for (int i = 0; i < 8; ++i) {
            int f   = i * 256 + tid;     // 0..2047
            int row = f >> 4;
            int kq  = f & 15;
            float4 va = __ldg(reinterpret_cast<const float4*>(
                g_S + (size_t)(block_row + row) * D + kc * BK + kq * 4));
            uint4 ta = make_uint4(f2tf32(va.x), f2tf32(va.y), f2tf32(va.z), f2tf32(va.w));
            *reinterpret_cast<uint4*>(As + row * LDS_PAD + kq * 4) = ta;

            float4 vb = __ldg(reinterpret_cast<const float4*>(
                g_Wt + (size_t)row * D + kc * BK + kq * 4));
            uint4 tb = make_uint4(f2tf32(vb.x), f2tf32(vb.y), f2tf32(vb.z), f2tf32(vb.w));
            *reinterpret_cast<uint4*>(Bs + row * LDS_PAD + kq * 4) = tb;
        }
        __syncthreads();

        // ---- 8 k-steps of k=8 ----
        #pragma unroll
        for (int ks = 0; ks < 8; ++ks) {
            int k0 = ks * 8;
            uint32_t a[2][4];
            #pragma unroll
            for (int mt = 0; mt < 2; ++mt) {
                const uint32_t* ap = reinterpret_cast<const uint32_t*>(
                    As + (wr + mt * 16 + gq) * LDS_PAD + k0 + tg);
                a[mt][0] = ap[0];
                a[mt][2] = ap[4];
                const uint32_t* ap8 = reinterpret_cast<const uint32_t*>(
                    As + (wr + mt * 16 + gq + 8) * LDS_PAD + k0 + tg);
                a[mt][1] = ap8[0];
                a[mt][3] = ap8[4];
            }
            uint32_t b[8][2];
            #pragma unroll
            for (int nt = 0; nt < 8; ++nt) {
                const uint32_t* bp = reinterpret_cast<const uint32_t*>(
                    Bs + (wc + nt * 8 + gq) * LDS_PAD + k0 + tg);
                b[nt][0] = bp[0];
                b[nt][1] = bp[4];
            }
            #pragma unroll
            for (int mt = 0; mt < 2; ++mt)
                #pragma unroll
                for (int nt = 0; nt < 8; ++nt)
                    mma_tf32(acc[mt][nt][0], acc[mt][nt][1],
                             acc[mt][nt][2], acc[mt][nt][3],
                             a[mt][0], a[mt][1], a[mt][2], a[mt][3],
                             b[nt][0], b[nt][1]);
        }
    }

    // ---- epilogue: tanh + float2 stores ----
    #pragma unroll
    for (int mt = 0; mt < 2; ++mt) {
        int r0 = block_row + wr + mt * 16 + gq;
        int r1 = r0 + 8;
        #pragma unroll
        for (int nt = 0; nt < 8; ++nt) {
            int col = wc + nt * 8 + tg * 2;
            if (r0 < M) {
                float2 o0;
                o0.x = tanhf(acc[mt][nt][0]);
                o0.y = tanhf(acc[mt][nt][1]);
                *reinterpret_cast<float2*>(out + (size_t)r0 * D + col) = o0;
            }
            if (r1 < M) {
                float2 o1;
                o1.x = tanhf(acc[mt][nt][2]);
                o1.y = tanhf(acc[mt][nt][3]);
                *reinterpret_cast<float2*>(out + (size_t)r1 * D + col) = o1;
            }
        }
    }
}

// ---------------------------------------------------------------------------
// Launch
// ---------------------------------------------------------------------------
extern "C" void kernel_launch(void* const* d_in, const int* in_sizes, int n_in,
                              void* d_out, int out_size)
{
    const float* values = (const float*)d_in[0];   // [N_SRC, 128] f32
    const float* Wmat   = (const float*)d_in[1];   // [128, 128] f32
    const int*   gidx   = (const int*)d_in[2];     // [E] int32
    const int*   seg    = (const int*)d_in[3];     // [E] int32, sorted

    int E     = in_sizes[2];
    int n_out = out_size / D;
    float* out = (float*)d_out;

    static int smem_set = 0;
    if (!smem_set) {
        cudaFuncSetAttribute(gemm_tanh_mma,
                             cudaFuncAttributeMaxDynamicSharedMemorySize,
                             SMEM_FLOATS * (int)sizeof(float));
        smem_set = 1;
    }

    transpose_W<<<16, dim3(32, 8)>>>(Wmat);
    init_row_start<<<(n_out + 256) / 256, 256>>>(n_out, E);
    mark_boundaries<<<(E + 255) / 256, 256>>>(seg, E);
    seg_gather_sum<<<(n_out * 32 + 255) / 256, 256>>>(values, gidx, n_out, E);
    gemm_tanh_mma<<<(n_out + 127) / 128, 256, SMEM_FLOATS * sizeof(float)>>>(out, n_out);
}

// round 14
// speedup vs baseline: 1.0127x; 1.0122x over previous
#include <cuda_runtime.h>
#include <cstdint>

#define D        128
#define MAX_OUT  100000
#define M_PAD    100352   // 784*128: tile-overrun padding for g_S reads

// Scratch (allocation-free rule: __device__ globals; zero-initialized)
__device__ float g_S[(size_t)M_PAD * D];   // segment sums (pad rows stay zero)
__device__ float g_Wt[D * D];              // W transposed: Wt[n][k] = W[k][n]
__device__ int   g_row_start[MAX_OUT + 1];

// ---------------------------------------------------------------------------
// helpers
// ---------------------------------------------------------------------------
static __device__ __forceinline__ uint32_t f2tf32(float f) {
    uint32_t r;
    asm("cvt.rna.tf32.f32 %0, %1;" : "=r"(r) : "f"(f));
    return r;
}
static __device__ __forceinline__ void mma_tf32(
    float& c0, float& c1, float& c2, float& c3,
    uint32_t a0, uint32_t a1, uint32_t a2, uint32_t a3,
    uint32_t b0, uint32_t b1)
{
    asm volatile(
        "mma.sync.aligned.m16n8k8.row.col.f32.tf32.tf32.f32 "
        "{%0,%1,%2,%3}, {%4,%5,%6,%7}, {%8,%9}, {%0,%1,%2,%3};"
        : "+f"(c0), "+f"(c1), "+f"(c2), "+f"(c3)
        : "r"(a0), "r"(a1), "r"(a2), "r"(a3), "r"(b0), "r"(b1));
}

// ---------------------------------------------------------------------------
// transpose W (128x128) into g_Wt.  grid=16 (4x4 tiles), block=(32,8)
// ---------------------------------------------------------------------------
__global__ void transpose_W(const float* __restrict__ W) {
    __shared__ float t[32][33];
    int bx = blockIdx.x & 3, by = blockIdx.x >> 2;
    int x = bx * 32 + threadIdx.x;
    #pragma unroll
    for (int i = 0; i < 4; ++i) {
        int y = by * 32 + threadIdx.y * 4 + i;
        t[threadIdx.y * 4 + i][threadIdx.x] = W[y * D + x];
    }
    __syncthreads();
    #pragma unroll
    for (int i = 0; i < 4; ++i) {
        int n = bx * 32 + threadIdx.y * 4 + i;
        g_Wt[n * D + by * 32 + threadIdx.x] = t[threadIdx.x][threadIdx.y * 4 + i];
    }
}

// ---------------------------------------------------------------------------
// segment CSR construction, single kernel (init merged in):
//   edge e>0 :  fill (seg[e-1], seg[e]]   with e
//   edge 0   :  fill [0, seg[0]]          with 0
//   edge E-1 :  also fill (seg[E-1], n_out] with E   (sentinel + trailing)
// ---------------------------------------------------------------------------
__global__ void mark_boundaries(const int* __restrict__ seg, int E, int n_out) {
    int e = blockIdx.x * blockDim.x + threadIdx.x;
    if (e >= E) return;
    int s  = seg[e];
    int sp = (e == 0) ? -1 : seg[e - 1];
    for (int t = sp + 1; t <= s; ++t) g_row_start[t] = e;
    if (e == E - 1) {
        for (int t = s + 1; t <= n_out; ++t) g_row_start[t] = E;
    }
}

// ---------------------------------------------------------------------------
// warp-per-segment gather-sum with coalesced index prefetch.
// Lane l owns float4 slice [4l,4l+4). One coalesced load fetches up to 32
// edge indices into registers; value-load addresses then come from shfl only
// (no memory dependency in the loop). Segments >32 edges take a rare tail.
// ---------------------------------------------------------------------------
__global__ __launch_bounds__(256) void seg_gather_sum(
    const float* __restrict__ values,
    const int* __restrict__ gidx,
    int n_out, int E)
{
    int warp = (blockIdx.x * blockDim.x + threadIdx.x) >> 5;
    if (warp >= n_out) return;
    int lane = threadIdx.x & 31;
    int c = lane * 4;

    int e0 = g_row_start[warp];
    int e1 = g_row_start[warp + 1];
    int cnt = e1 - e0;

    // one coalesced 128B index load covers up to 32 edges
    int ei = e0 + lane;
    int idx_l = (ei < E) ? __ldg(gidx + ei) : 0;

    float4 a0 = make_float4(0.f, 0.f, 0.f, 0.f);
    float4 a1 = make_float4(0.f, 0.f, 0.f, 0.f);
    float4 a2 = make_float4(0.f, 0.f, 0.f, 0.f);
    float4 a3 = make_float4(0.f, 0.f, 0.f, 0.f);

    int n32 = cnt < 32 ? cnt : 32;
    int j = 0;
    for (; j + 4 <= n32; j += 4) {
        long long i0 = (long long)__shfl_sync(0xFFFFFFFFu, idx_l, j);
        long long i1 = (long long)__shfl_sync(0xFFFFFFFFu, idx_l, j + 1);
        long long i2 = (long long)__shfl_sync(0xFFFFFFFFu, idx_l, j + 2);
        long long i3 = (long long)__shfl_sync(0xFFFFFFFFu, idx_l, j + 3);
        float4 v0 = __ldg(reinterpret_cast<const float4*>(values + i0 * D + c));
        float4 v1 = __ldg(reinterpret_cast<const float4*>(values + i1 * D + c));
        float4 v2 = __ldg(reinterpret_cast<const float4*>(values + i2 * D + c));
        float4 v3 = __ldg(reinterpret_cast<const float4*>(values + i3 * D + c));
        a0.x += v0.x; a0.y += v0.y; a0.z += v0.z; a0.w += v0.w;
        a1.x += v1.x; a1.y += v1.y; a1.z += v1.z; a1.w += v1.w;
        a2.x += v2.x; a2.y += v2.y; a2.z += v2.z; a2.w += v2.w;
        a3.x += v3.x; a3.y += v3.y; a3.z += v3.z; a3.w += v3.w;
    }
    for (; j < n32; ++j) {
        long long i0 = (long long)__shfl_sync(0xFFFFFFFFu, idx_l, j);
        float4 v0 = __ldg(reinterpret_cast<const float4*>(values + i0 * D + c));
        a0.x += v0.x; a0.y += v0.y; a0.z += v0.z; a0.w += v0.w;
    }

    // rare long-segment tail (cnt > 32): broadcast index loads
    for (int e = e0 + 32; e < e1; ++e) {
        long long i0 = (long long)__ldg(gidx + e);
        float4 v0 = __ldg(reinterpret_cast<const float4*>(values + i0 * D + c));
        a1.x += v0.x; a1.y += v0.y; a1.z += v0.z; a1.w += v0.w;
    }

    float4 acc;
    acc.x = (a0.x + a1.x) + (a2.x + a3.x);
    acc.y = (a0.y + a1.y) + (a2.y + a3.y);
    acc.z = (a0.z + a1.z) + (a2.z + a3.z);
    acc.w = (a0.w + a1.w) + (a2.w + a3.w);
    *reinterpret_cast<float4*>(g_S + (size_t)warp * D + c) = acc;
}

// ---------------------------------------------------------------------------
// tf32 mma.sync GEMM + tanh (byte-identical to the 129.3us baseline).
// CTA: 128(M) x 128(N), K chunked by 64. 8 warps: (wid&3)->m32, (wid>>2)->n64.
// Smem padded [128][68]: fragment loads are bank-conflict-free.
// ---------------------------------------------------------------------------
#define BK      64
#define LDS_PAD 68                       // 64 + 4 floats
#define AS_FLOATS (128 * LDS_PAD)
#define SMEM_FLOATS (2 * AS_FLOATS)      // As + Bs

__global__ __launch_bounds__(256, 2) void gemm_tanh_mma(
    float* __restrict__ out, int M)
{
    extern __shared__ float smem[];
    float* As = smem;                    // [128][68] tf32 bits (as float storage)
    float* Bs = smem + AS_FLOATS;        // [128][68]

    int tid  = threadIdx.x;
    int wid  = tid >> 5;
    int lane = tid & 31;
    int wr   = (wid & 3) * 32;           // warp m offset
    int wc   = (wid >> 2) * 64;          // warp n offset
    int gq   = lane >> 2;                // groupID 0..7
    int tg   = lane & 3;                 // thread-in-group 0..3

    int block_row = blockIdx.x * 128;

    float acc[2][8][4];
    #pragma unroll
    for (int mt = 0; mt < 2; ++mt)
        #pragma unroll
        for (int nt = 0; nt < 8; ++nt)
            #pragma unroll
            for (int q = 0; q < 4; ++q) acc[mt][nt][q] = 0.f;

    for (int kc = 0; kc < 2; ++kc) {
        // ---- stage A and B k-chunk, converting to tf32 ----
        __syncthreads();
        #pragma unroll
        for (int i = 0; i < 8; ++i) {
            int f   = i * 256 + tid;     // 0..2047
            int row = f >> 4;
            int kq  = f & 15;
            float4 va = __ldg(reinterpret_cast<const float4*>(
                g_S + (size_t)(block_row + row) * D + kc * BK + kq * 4));
            uint4 ta = make_uint4(f2tf32(va.x), f2tf32(va.y), f2tf32(va.z), f2tf32(va.w));
            *reinterpret_cast<uint4*>(As + row * LDS_PAD + kq * 4) = ta;

            float4 vb = __ldg(reinterpret_cast<const float4*>(
                g_Wt + (size_t)row * D + kc * BK + kq * 4));
            uint4 tb = make_uint4(f2tf32(vb.x), f2tf32(vb.y), f2tf32(vb.z), f2tf32(vb.w));
            *reinterpret_cast<uint4*>(Bs + row * LDS_PAD + kq * 4) = tb;
        }
        __syncthreads();

        // ---- 8 k-steps of k=8 ----
        #pragma unroll
        for (int ks = 0; ks < 8; ++ks) {
            int k0 = ks * 8;
            uint32_t a[2][4];
            #pragma unroll
            for (int mt = 0; mt < 2; ++mt) {
                const uint32_t* ap = reinterpret_cast<const uint32_t*>(
                    As + (wr + mt * 16 + gq) * LDS_PAD + k0 + tg);
                a[mt][0] = ap[0];
                a[mt][2] = ap[4];
                const uint32_t* ap8 = reinterpret_cast<const uint32_t*>(
                    As + (wr + mt * 16 + gq + 8) * LDS_PAD + k0 + tg);
                a[mt][1] = ap8[0];
                a[mt][3] = ap8[4];
            }
            uint32_t b[8][2];
            #pragma unroll
            for (int nt = 0; nt < 8; ++nt) {
                const uint32_t* bp = reinterpret_cast<const uint32_t*>(
                    Bs + (wc + nt * 8 + gq) * LDS_PAD + k0 + tg);
                b[nt][0] = bp[0];
                b[nt][1] = bp[4];
            }
            #pragma unroll
            for (int mt = 0; mt < 2; ++mt)
                #pragma unroll
                for (int nt = 0; nt < 8; ++nt)
                    mma_tf32(acc[mt][nt][0], acc[mt][nt][1],
                             acc[mt][nt][2], acc[mt][nt][3],
                             a[mt][0], a[mt][1], a[mt][2], a[mt][3],
                             b[nt][0], b[nt][1]);
        }
    }

    // ---- epilogue: tanh + float2 stores ----
    #pragma unroll
    for (int mt = 0; mt < 2; ++mt) {
        int r0 = block_row + wr + mt * 16 + gq;
        int r1 = r0 + 8;
        #pragma unroll
        for (int nt = 0; nt < 8; ++nt) {
            int col = wc + nt * 8 + tg * 2;
            if (r0 < M) {
                float2 o0;
                o0.x = tanhf(acc[mt][nt][0]);
                o0.y = tanhf(acc[mt][nt][1]);
                *reinterpret_cast<float2*>(out + (size_t)r0 * D + col) = o0;
            }
            if (r1 < M) {
                float2 o1;
                o1.x = tanhf(acc[mt][nt][2]);
                o1.y = tanhf(acc[mt][nt][3]);
                *reinterpret_cast<float2*>(out + (size_t)r1 * D + col) = o1;
            }
        }
    }
}

// ---------------------------------------------------------------------------
// Launch
// ---------------------------------------------------------------------------
extern "C" void kernel_launch(void* const* d_in, const int* in_sizes, int n_in,
                              void* d_out, int out_size)
{
    const float* values = (const float*)d_in[0];   // [N_SRC, 128] f32
    const float* Wmat   = (const float*)d_in[1];   // [128, 128] f32
    const int*   gidx   = (const int*)d_in[2];     // [E] int32
    const int*   seg    = (const int*)d_in[3];     // [E] int32, sorted

    int E     = in_sizes[2];
    int n_out = out_size / D;
    float* out = (float*)d_out;

    static int smem_set = 0;
    if (!smem_set) {
        cudaFuncSetAttribute(gemm_tanh_mma,
                             cudaFuncAttributeMaxDynamicSharedMemorySize,
                             SMEM_FLOATS * (int)sizeof(float));
        smem_set = 1;
    }

    transpose_W<<<16, dim3(32, 8)>>>(Wmat);
    mark_boundaries<<<(E + 255) / 256, 256>>>(seg, E, n_out);
    seg_gather_sum<<<(n_out * 32 + 255) / 256, 256>>>(values, gidx, n_out, E);
    gemm_tanh_mma<<<(n_out + 127) / 128, 256, SMEM_FLOATS * sizeof(float)>>>(out, n_out);
}